// round 6
// baseline (speedup 1.0000x reference)
#include <cuda_runtime.h>
#include <cuda_fp16.h>
#include <cstdint>

// Problem dims
#define NL 16
#define DH 128
#define G4 512      // 4*H
#define BB 32
#define TT 512
#define NH 2048     // N*H
#define STRD 136    // padded halves per row (conflict-free LDS)

// x_proj scratch: [n][t][b][4H] fp16, bias pre-added = 256 MB
__device__ __half g_xp16[(size_t)NL * TT * BB * G4];

// ---------------- mma.sync m16n8k16 (fp16 in, fp32 acc) ----------------
__device__ __forceinline__ void mma16816(float* d, const uint32_t* a,
                                         uint32_t b0, uint32_t b1) {
    asm volatile("mma.sync.aligned.m16n8k16.row.col.f32.f16.f16.f32 "
                 "{%0,%1,%2,%3}, {%4,%5,%6,%7}, {%8,%9}, {%0,%1,%2,%3};"
                 : "+f"(d[0]), "+f"(d[1]), "+f"(d[2]), "+f"(d[3])
                 : "r"(a[0]), "r"(a[1]), "r"(a[2]), "r"(a[3]), "r"(b0), "r"(b1));
}

// HW tanh (1 MUFU); sigma(x) = 0.5*tanh(x/2)+0.5
__device__ __forceinline__ float tanh_apx(float x) {
    float t;
    asm("tanh.approx.f32 %0, %1;" : "=f"(t) : "f"(x));
    return t;
}
__device__ __forceinline__ float sigm_apx(float x) {
    return fmaf(0.5f, tanh_apx(0.5f * x), 0.5f);
}

// =================================================================
// Phase 1: x_proj16[n][t][b][g] = W_ih[n].x[b,t,nI:] + b_ih + b_hh
// Swapped operands: A = x (M = t), B = W (N = g) -> D cols contiguous in g
// grid (4 t-tiles, 4 b-groups of 8, 16 n) = 256 CTAs, 512 threads
// =================================================================
#define P1_TB 128
#define P1_SMEM (G4 * STRD * 2 + 2 * P1_TB * STRD * 2)   // 139264 + 69632

__global__ void __launch_bounds__(512, 1) wlstm_xproj(
    const float* __restrict__ x, const float* __restrict__ Wih,
    const float* __restrict__ bih, const float* __restrict__ bhh)
{
    extern __shared__ char p1smem[];
    __half* ws  = (__half*)p1smem;                        // [512 g][STRD]
    __half* xs0 = (__half*)(p1smem + G4 * STRD * 2);      // [128 t][STRD]
    __half* xs1 = xs0 + P1_TB * STRD;

    const int tid = threadIdx.x, wid = tid >> 5, lane = tid & 31;
    const int g0 = lane >> 2, cq = lane & 3;
    const int n = blockIdx.z, bg = blockIdx.y, t0 = blockIdx.x * P1_TB;

    // ---- W_ih[n] fp32 -> fp16 SMEM [g][k] (acts as B, col-major k x n)
    const float4* W4 = (const float4*)(Wih + (size_t)n * G4 * DH);
#pragma unroll 4
    for (int i = tid; i < G4 * DH / 4; i += 512) {
        float4 w = W4[i];
        int r = i >> 5, k = (i & 31) * 4;
        __half2 h01 = __floats2half2_rn(w.x, w.y);
        __half2 h23 = __floats2half2_rn(w.z, w.w);
        uint2 v = { *(uint32_t*)&h01, *(uint32_t*)&h23 };
        *(uint2*)(ws + r * STRD + k) = v;
    }
    // ---- x(b0) tile
    {
        int b = bg * 8;
#pragma unroll 4
        for (int i = tid; i < P1_TB * DH / 4; i += 512) {
            int tl = i >> 5, c4 = (i & 31) * 4;
            float4 w = *(const float4*)(x + ((size_t)b * TT + t0 + tl) * NH + n * DH + c4);
            __half2 h01 = __floats2half2_rn(w.x, w.y);
            __half2 h23 = __floats2half2_rn(w.z, w.w);
            uint2 v = { *(uint32_t*)&h01, *(uint32_t*)&h23 };
            *(uint2*)(xs0 + tl * STRD + c4) = v;
        }
    }
    // bias for this warp's 32 g-columns (D cols = 2cq, 2cq+1 per n-tile)
    float bsv[4][2];
#pragma unroll
    for (int nt = 0; nt < 4; nt++) {
        int g = wid * 32 + nt * 8 + 2 * cq;
        bsv[nt][0] = bih[n * G4 + g]     + bhh[n * G4 + g];
        bsv[nt][1] = bih[n * G4 + g + 1] + bhh[n * G4 + g + 1];
    }
    __syncthreads();

    const uint32_t* ws32 = (const uint32_t*)ws;

    for (int bl = 0; bl < 8; bl++) {
        int b = bg * 8 + bl;
        __half* xs = (bl & 1) ? xs1 : xs0;
        __half* xn = (bl & 1) ? xs0 : xs1;
        // prefetch next batch's x tile
        if (bl + 1 < 8) {
            int b2 = b + 1;
#pragma unroll 4
            for (int i = tid; i < P1_TB * DH / 4; i += 512) {
                int tl = i >> 5, c4 = (i & 31) * 4;
                float4 w = *(const float4*)(x + ((size_t)b2 * TT + t0 + tl) * NH + n * DH + c4);
                __half2 h01 = __floats2half2_rn(w.x, w.y);
                __half2 h23 = __floats2half2_rn(w.z, w.w);
                uint2 v = { *(uint32_t*)&h01, *(uint32_t*)&h23 };
                *(uint2*)(xn + tl * STRD + c4) = v;
            }
        }
        const uint32_t* xs32 = (const uint32_t*)xs;
        __half* ob = g_xp16 + ((size_t)(n * TT + t0) * BB + b) * G4;

        for (int hf = 0; hf < 2; hf++) {
            // B-frags for 2 n-tiles (W columns)
            uint32_t bf[2][8][2];
#pragma unroll
            for (int p = 0; p < 2; p++) {
                int col = wid * 32 + (hf * 2 + p) * 8 + g0;
#pragma unroll
                for (int kc = 0; kc < 8; kc++) {
                    bf[p][kc][0] = ws32[col * (STRD / 2) + kc * 8 + cq];
                    bf[p][kc][1] = ws32[col * (STRD / 2) + kc * 8 + cq + 4];
                }
            }
#pragma unroll 1
            for (int mt = 0; mt < 8; mt++) {
                // A-frags (x rows = t)
                uint32_t a[8][4];
                int r0 = mt * 16 + g0;
#pragma unroll
                for (int kc = 0; kc < 8; kc++) {
                    int kw = kc * 8 + cq;
                    a[kc][0] = xs32[r0 * (STRD / 2) + kw];
                    a[kc][1] = xs32[(r0 + 8) * (STRD / 2) + kw];
                    a[kc][2] = xs32[r0 * (STRD / 2) + kw + 4];
                    a[kc][3] = xs32[(r0 + 8) * (STRD / 2) + kw + 4];
                }
                float d[2][4];
#pragma unroll
                for (int p = 0; p < 2; p++)
#pragma unroll
                    for (int q = 0; q < 4; q++) d[p][q] = 0.0f;
#pragma unroll
                for (int kc = 0; kc < 8; kc++)
#pragma unroll
                    for (int p = 0; p < 2; p++)
                        mma16816(d[p], a[kc], bf[p][kc][0], bf[p][kc][1]);
                // store: rows t = r0, r0+8 ; cols g contiguous pairs
                size_t ro0 = (size_t)(mt * 16 + g0) * (BB * G4);
                size_t ro1 = ro0 + (size_t)8 * (BB * G4);
#pragma unroll
                for (int p = 0; p < 2; p++) {
                    int nt = hf * 2 + p;
                    int g = wid * 32 + nt * 8 + 2 * cq;
                    __half2 v0 = __floats2half2_rn(d[p][0] + bsv[nt][0],
                                                   d[p][1] + bsv[nt][1]);
                    __half2 v1 = __floats2half2_rn(d[p][2] + bsv[nt][0],
                                                   d[p][3] + bsv[nt][1]);
                    *(__half2*)(ob + ro0 + g) = v0;
                    *(__half2*)(ob + ro1 + g) = v1;
                }
            }
        }
        __syncthreads();   // xs reads done + xn stores visible
    }
}

// =================================================================
// Phase 2: persistent recurrence. grid 128 = (n, bc of 4 batches),
// 512 threads. W_hh in regs; split accumulator chains; z via SMEM;
// one (j,b) LSTM state per thread; all-approx activations.
// =================================================================
#define ZSTR 520

__global__ void __launch_bounds__(512, 1) wlstm_rec(
    const float* __restrict__ Whh, float* __restrict__ out)
{
    __shared__ __half hs[2][8][STRD];
    __shared__ float  zs[4 * ZSTR];

    const int tid = threadIdx.x, wid = tid >> 5, lane = tid & 31;
    const int g0 = lane >> 2, cq = lane & 3;
    const int n = blockIdx.x >> 3, bc = blockIdx.x & 7;

    for (int i = tid; i < 2 * 8 * STRD; i += 512) ((__half*)hs)[i] = __float2half(0.0f);

    // ---- W_hh[n] -> A-fragments (warp wid owns m-tiles {wid, wid+16})
    uint32_t a[2][8][4];
    const float* W = Whh + (size_t)n * G4 * DH;
#pragma unroll
    for (int ti = 0; ti < 2; ti++) {
        int r0 = (wid + 16 * ti) * 16 + g0;
#pragma unroll
        for (int kc = 0; kc < 8; kc++) {
            int k0 = kc * 16 + cq * 2;
            float2 w00 = *(const float2*)(W + (size_t)r0 * DH + k0);
            float2 w10 = *(const float2*)(W + (size_t)(r0 + 8) * DH + k0);
            float2 w01 = *(const float2*)(W + (size_t)r0 * DH + k0 + 8);
            float2 w11 = *(const float2*)(W + (size_t)(r0 + 8) * DH + k0 + 8);
            __half2 h00 = __floats2half2_rn(w00.x, w00.y);
            __half2 h10 = __floats2half2_rn(w10.x, w10.y);
            __half2 h01 = __floats2half2_rn(w01.x, w01.y);
            __half2 h11 = __floats2half2_rn(w11.x, w11.y);
            a[ti][kc][0] = *(uint32_t*)&h00;
            a[ti][kc][1] = *(uint32_t*)&h10;
            a[ti][kc][2] = *(uint32_t*)&h01;
            a[ti][kc][3] = *(uint32_t*)&h11;
        }
    }

    const int j  = tid & 127;
    const int bl = tid >> 7;
    const int b  = bc * 4 + bl;

    const __half* xq = g_xp16 + ((size_t)(n * TT) * BB + b) * G4 + j;
    float* ob = out + (size_t)b * TT * NH + n * DH + j;

    float xp[4];
#pragma unroll
    for (int g = 0; g < 4; g++) xp[g] = __half2float(xq[g * 128]);

    float cst = 0.0f, hst = 0.0f;
    __syncthreads();

#pragma unroll 2
    for (int t = 0; t < TT; t++) {
        const uint32_t* hb = (const uint32_t*)hs[t & 1];
        // ---- z = W_hh . h_{t-1}, two accumulator chains (even/odd kc)
        float dA[2][4], dB[2][4];
#pragma unroll
        for (int ti = 0; ti < 2; ti++)
#pragma unroll
            for (int q = 0; q < 4; q++) { dA[ti][q] = 0.0f; dB[ti][q] = 0.0f; }
#pragma unroll
        for (int kc = 0; kc < 8; kc += 2) {
            uint32_t b0 = hb[g0 * (STRD / 2) + kc * 8 + cq];
            uint32_t b1 = hb[g0 * (STRD / 2) + kc * 8 + cq + 4];
            uint32_t c0 = hb[g0 * (STRD / 2) + (kc + 1) * 8 + cq];
            uint32_t c1 = hb[g0 * (STRD / 2) + (kc + 1) * 8 + cq + 4];
#pragma unroll
            for (int ti = 0; ti < 2; ti++) mma16816(dA[ti], a[ti][kc], b0, b1);
#pragma unroll
            for (int ti = 0; ti < 2; ti++) mma16816(dB[ti], a[ti][kc + 1], c0, c1);
        }
        if (cq < 2) {
#pragma unroll
            for (int ti = 0; ti < 2; ti++) {
                int r0 = (wid + 16 * ti) * 16 + g0;
                zs[(2 * cq) * ZSTR + r0]         = dA[ti][0] + dB[ti][0];
                zs[(2 * cq + 1) * ZSTR + r0]     = dA[ti][1] + dB[ti][1];
                zs[(2 * cq) * ZSTR + r0 + 8]     = dA[ti][2] + dB[ti][2];
                zs[(2 * cq + 1) * ZSTR + r0 + 8] = dA[ti][3] + dB[ti][3];
            }
        }
        __syncthreads();

        // ---- epilogue: one state per thread
        float zi = zs[bl * ZSTR + j]       + xp[0];
        float zf = zs[bl * ZSTR + 128 + j] + xp[1];
        float zg = zs[bl * ZSTR + 256 + j] + xp[2];
        float zo = zs[bl * ZSTR + 384 + j] + xp[3];
        // prefetch x_proj(t+1) into xp (full-step latency cover)
        if (t + 1 < TT) {
            const __half* xn = xq + (size_t)(t + 1) * (BB * G4);
#pragma unroll
            for (int g = 0; g < 4; g++) xp[g] = __half2float(xn[g * 128]);
        }
        float ig = sigm_apx(zi);
        float fg = sigm_apx(zf);
        float gg = tanh_apx(zg);
        float og = sigm_apx(zo);
        cst = fg * cst + ig * gg;
        hst = og * tanh_apx(cst);

        hs[(t + 1) & 1][bl][j] = __float2half(hst);
        ob[(size_t)t * NH] = hst;
        __syncthreads();
    }

    // h_n, c_n: out = [output | h_n | c_n]
    float* hn = out + (size_t)BB * TT * NH + (size_t)b * NH + n * DH + j;
    hn[0] = hst;
    hn[(size_t)BB * NH] = cst;
}

extern "C" void kernel_launch(void* const* d_in, const int* in_sizes, int n_in,
                              void* d_out, int out_size) {
    const float* x   = (const float*)d_in[0];
    const float* Wih = (const float*)d_in[1];
    const float* Whh = (const float*)d_in[2];
    const float* bih = (const float*)d_in[3];
    const float* bhh = (const float*)d_in[4];
    float* out = (float*)d_out;

    cudaFuncSetAttribute(wlstm_xproj,
                         cudaFuncAttributeMaxDynamicSharedMemorySize, P1_SMEM);

    dim3 g1(TT / P1_TB, BB / 8, NL);   // (4, 4, 16) = 256 CTAs
    wlstm_xproj<<<g1, 512, P1_SMEM>>>(x, Wih, bih, bhh);
    wlstm_rec<<<NL * 8, 512>>>(Whh, out);
}

// round 7
// speedup vs baseline: 1.2591x; 1.2591x over previous
#include <cuda_runtime.h>
#include <cuda_fp16.h>
#include <cstdint>

// Problem dims
#define NL 16
#define DH 128
#define G4 512      // 4*H
#define BB 32
#define TT 512
#define NH 2048     // N*H
#define STRD 136    // padded halves per row (conflict-free LDS)

// x_proj scratch: [n][t][b][4H] fp16, bias pre-added = 256 MB
__device__ __half g_xp16[(size_t)NL * TT * BB * G4];

// ---------------- mma.sync m16n8k16 (fp16 in, fp32 acc) ----------------
__device__ __forceinline__ void mma16816(float* d, const uint32_t* a,
                                         uint32_t b0, uint32_t b1) {
    asm volatile("mma.sync.aligned.m16n8k16.row.col.f32.f16.f16.f32 "
                 "{%0,%1,%2,%3}, {%4,%5,%6,%7}, {%8,%9}, {%0,%1,%2,%3};"
                 : "+f"(d[0]), "+f"(d[1]), "+f"(d[2]), "+f"(d[3])
                 : "r"(a[0]), "r"(a[1]), "r"(a[2]), "r"(a[3]), "r"(b0), "r"(b1));
}

// HW tanh (1 MUFU); sigma(x) = 0.5*tanh(x/2)+0.5
__device__ __forceinline__ float tanh_apx(float x) {
    float t;
    asm("tanh.approx.f32 %0, %1;" : "=f"(t) : "f"(x));
    return t;
}
__device__ __forceinline__ float sigm_apx(float x) {
    return fmaf(0.5f, tanh_apx(0.5f * x), 0.5f);
}

// =================================================================
// Phase 1: x_proj16[n][t][b][r] = W_ih[n].x[b,t,nI:] + b_ih + b_hh
// (R5 structure: A = W rows = gates, B = x cols = t)
// grid (4 t-tiles, 8 b-groups of 4, 16 n) = 512 CTAs, 512 threads
// =================================================================
#define P1_TB 128
#define P1_SMEM ((G4 * STRD + P1_TB * STRD) * 2)

__global__ void __launch_bounds__(512, 1) wlstm_xproj(
    const float* __restrict__ x, const float* __restrict__ Wih,
    const float* __restrict__ bih, const float* __restrict__ bhh)
{
    extern __shared__ char p1smem[];
    __half* ws = (__half*)p1smem;                       // [512][STRD]
    __half* xs = (__half*)(p1smem + G4 * STRD * 2);     // [128][STRD]

    const int tid = threadIdx.x, wid = tid >> 5, lane = tid & 31;
    const int g0 = lane >> 2, cq = lane & 3;
    const int n = blockIdx.z, bg = blockIdx.y, t0 = blockIdx.x * P1_TB;

    // ---- W_ih[n] fp32 -> fp16 SMEM (float4 loads, MLP-deep)
    const float4* W4 = (const float4*)(Wih + (size_t)n * G4 * DH);
#pragma unroll 4
    for (int i = tid; i < G4 * DH / 4; i += 512) {
        float4 w = W4[i];
        int r = i >> 5, k = (i & 31) * 4;
        __half2 h01 = __floats2half2_rn(w.x, w.y);
        __half2 h23 = __floats2half2_rn(w.z, w.w);
        uint2 v = { *(uint32_t*)&h01, *(uint32_t*)&h23 };
        *(uint2*)(ws + r * STRD + k) = v;
    }
    // ---- x(b0) tile [128 t][128 i]
    {
        int b = bg * 4;
#pragma unroll 4
        for (int i = tid; i < P1_TB * DH / 4; i += 512) {
            int tl = i >> 5, c4 = (i & 31) * 4;
            float4 w = *(const float4*)(x + ((size_t)b * TT + t0 + tl) * NH + n * DH + c4);
            __half2 h01 = __floats2half2_rn(w.x, w.y);
            __half2 h23 = __floats2half2_rn(w.z, w.w);
            uint2 v = { *(uint32_t*)&h01, *(uint32_t*)&h23 };
            *(uint2*)(xs + tl * STRD + c4) = v;
        }
    }
    __syncthreads();

    // ---- A-fragments: warp wid owns m-tiles {2*wid, 2*wid+1}
    uint32_t a[2][8][4];
    const uint32_t* ws32 = (const uint32_t*)ws;
#pragma unroll
    for (int ti = 0; ti < 2; ti++) {
        int r0 = (2 * wid + ti) * 16 + g0;
#pragma unroll
        for (int kc = 0; kc < 8; kc++) {
            int kw = kc * 8 + cq;
            a[ti][kc][0] = ws32[r0 * (STRD / 2) + kw];
            a[ti][kc][1] = ws32[(r0 + 8) * (STRD / 2) + kw];
            a[ti][kc][2] = ws32[r0 * (STRD / 2) + kw + 4];
            a[ti][kc][3] = ws32[(r0 + 8) * (STRD / 2) + kw + 4];
        }
    }
    // bias per D-row (gate rows r0, r0+8)
    float bsv[2][2];
#pragma unroll
    for (int ti = 0; ti < 2; ti++) {
        int r0 = (2 * wid + ti) * 16 + g0;
        bsv[ti][0] = bih[n * G4 + r0]     + bhh[n * G4 + r0];
        bsv[ti][1] = bih[n * G4 + r0 + 8] + bhh[n * G4 + r0 + 8];
    }

    const uint32_t* xs32 = (const uint32_t*)xs;
    for (int bl = 0; bl < 4; bl++) {
        int b = bg * 4 + bl;
        __half* ob = g_xp16 + ((size_t)(n * TT + t0) * BB + b) * G4;

        for (int nt = 0; nt < P1_TB / 8; nt++) {
            float d[2][4];
#pragma unroll
            for (int ti = 0; ti < 2; ti++)
#pragma unroll
                for (int q = 0; q < 4; q++) d[ti][q] = 0.0f;

            int col = nt * 8 + g0;
#pragma unroll
            for (int kc = 0; kc < 8; kc++) {
                uint32_t b0 = xs32[col * (STRD / 2) + kc * 8 + cq];
                uint32_t b1 = xs32[col * (STRD / 2) + kc * 8 + cq + 4];
#pragma unroll
                for (int ti = 0; ti < 2; ti++) mma16816(d[ti], a[ti][kc], b0, b1);
            }
            // D cols = t {2cq, 2cq+1}, rows {r0, r0+8}; bias folded here
            int tc = nt * 8 + 2 * cq;
#pragma unroll
            for (int ti = 0; ti < 2; ti++) {
                int r0 = (2 * wid + ti) * 16 + g0;
                ob[(size_t)tc * (BB * G4) + r0]           = __float2half(d[ti][0] + bsv[ti][0]);
                ob[(size_t)(tc + 1) * (BB * G4) + r0]     = __float2half(d[ti][1] + bsv[ti][0]);
                ob[(size_t)tc * (BB * G4) + r0 + 8]       = __float2half(d[ti][2] + bsv[ti][1]);
                ob[(size_t)(tc + 1) * (BB * G4) + r0 + 8] = __float2half(d[ti][3] + bsv[ti][1]);
            }
        }
        __syncthreads();   // all B-frag reads done before xs overwrite
        if (bl < 3) {
            int bn = bg * 4 + bl + 1;
#pragma unroll 4
            for (int i = tid; i < P1_TB * DH / 4; i += 512) {
                int tl = i >> 5, c4 = (i & 31) * 4;
                float4 w = *(const float4*)(x + ((size_t)bn * TT + t0 + tl) * NH + n * DH + c4);
                __half2 h01 = __floats2half2_rn(w.x, w.y);
                __half2 h23 = __floats2half2_rn(w.z, w.w);
                uint2 v = { *(uint32_t*)&h01, *(uint32_t*)&h23 };
                *(uint2*)(xs + tl * STRD + c4) = v;
            }
            __syncthreads();
        }
    }
}

// =================================================================
// Phase 2: persistent recurrence (R5 structure). grid 128, 512 thr.
// W_hh in regs (single accumulator chain); z via SMEM; one state
// per thread; all-approx activations; no bias (folded in xproj).
// =================================================================
#define ZSTR 520

__global__ void __launch_bounds__(512, 1) wlstm_rec(
    const float* __restrict__ Whh, float* __restrict__ out)
{
    __shared__ __half hs[2][8][STRD];   // double-buffered h tile [buf][bcol][j]
    __shared__ float  zs[4 * ZSTR];     // z exchange: [batch][512 gate rows]

    const int tid = threadIdx.x, wid = tid >> 5, lane = tid & 31;
    const int g0 = lane >> 2, cq = lane & 3;
    const int n = blockIdx.x >> 3, bc = blockIdx.x & 7;

    for (int i = tid; i < 2 * 8 * STRD; i += 512) ((__half*)hs)[i] = __float2half(0.0f);

    // ---- W_hh[n] -> A-fragments (warp wid owns m-tiles {wid, wid+16})
    uint32_t a[2][8][4];
    const float* W = Whh + (size_t)n * G4 * DH;
#pragma unroll
    for (int ti = 0; ti < 2; ti++) {
        int r0 = (wid + 16 * ti) * 16 + g0;
#pragma unroll
        for (int kc = 0; kc < 8; kc++) {
            int k0 = kc * 16 + cq * 2;
            float2 w00 = *(const float2*)(W + (size_t)r0 * DH + k0);
            float2 w10 = *(const float2*)(W + (size_t)(r0 + 8) * DH + k0);
            float2 w01 = *(const float2*)(W + (size_t)r0 * DH + k0 + 8);
            float2 w11 = *(const float2*)(W + (size_t)(r0 + 8) * DH + k0 + 8);
            __half2 h00 = __floats2half2_rn(w00.x, w00.y);
            __half2 h10 = __floats2half2_rn(w10.x, w10.y);
            __half2 h01 = __floats2half2_rn(w01.x, w01.y);
            __half2 h11 = __floats2half2_rn(w11.x, w11.y);
            a[ti][kc][0] = *(uint32_t*)&h00;
            a[ti][kc][1] = *(uint32_t*)&h10;
            a[ti][kc][2] = *(uint32_t*)&h01;
            a[ti][kc][3] = *(uint32_t*)&h11;
        }
    }

    const int j  = tid & 127;
    const int bl = tid >> 7;
    const int b  = bc * 4 + bl;

    const __half* xq = g_xp16 + ((size_t)(n * TT) * BB + b) * G4 + j;
    float* ob = out + (size_t)b * TT * NH + n * DH + j;

    float xpa[4], xpb[4];
#pragma unroll
    for (int g = 0; g < 4; g++) xpa[g] = __half2float(xq[g * 128]);

    float cst = 0.0f, hst = 0.0f;
    __syncthreads();

    auto step = [&](int t, float (&xpc)[4], float (&xpn)[4]) {
        // prefetch x_proj(t+1) early (hidden behind mma)
        if (t + 1 < TT) {
            const __half* xn = xq + (size_t)(t + 1) * (BB * G4);
#pragma unroll
            for (int g = 0; g < 4; g++) xpn[g] = __half2float(xn[g * 128]);
        }
        // ---- z = W_hh . h_{t-1}
        const uint32_t* hb = (const uint32_t*)hs[t & 1];
        float d[2][4];
#pragma unroll
        for (int ti = 0; ti < 2; ti++)
#pragma unroll
            for (int q = 0; q < 4; q++) d[ti][q] = 0.0f;
#pragma unroll
        for (int kc = 0; kc < 8; kc++) {
            uint32_t b0 = hb[g0 * (STRD / 2) + kc * 8 + cq];
            uint32_t b1 = hb[g0 * (STRD / 2) + kc * 8 + cq + 4];
#pragma unroll
            for (int ti = 0; ti < 2; ti++) mma16816(d[ti], a[ti][kc], b0, b1);
        }
        // stash z for real batches (D cols 0..3 <-> cq 0,1)
        if (cq < 2) {
#pragma unroll
            for (int ti = 0; ti < 2; ti++) {
                int r0 = (wid + 16 * ti) * 16 + g0;
                zs[(2 * cq) * ZSTR + r0]         = d[ti][0];
                zs[(2 * cq + 1) * ZSTR + r0]     = d[ti][1];
                zs[(2 * cq) * ZSTR + r0 + 8]     = d[ti][2];
                zs[(2 * cq + 1) * ZSTR + r0 + 8] = d[ti][3];
            }
        }
        __syncthreads();   // z visible to all

        // ---- epilogue: one state per thread (all-approx activations)
        float zi = zs[bl * ZSTR + j]       + xpc[0];
        float zf = zs[bl * ZSTR + 128 + j] + xpc[1];
        float zg = zs[bl * ZSTR + 256 + j] + xpc[2];
        float zo = zs[bl * ZSTR + 384 + j] + xpc[3];
        float ig = sigm_apx(zi);
        float fg = sigm_apx(zf);
        float gg = tanh_apx(zg);
        float og = sigm_apx(zo);
        cst = fg * cst + ig * gg;
        hst = og * tanh_apx(cst);

        ob[(size_t)t * NH] = hst;
        hs[(t + 1) & 1][bl][j] = __float2half(hst);
        __syncthreads();   // hs(t) visible + zs reads done before next mma
    };

    for (int t = 0; t < TT; t += 2) {
        step(t, xpa, xpb);
        step(t + 1, xpb, xpa);
    }

    // h_n, c_n: out = [output | h_n | c_n]
    float* hn = out + (size_t)BB * TT * NH + (size_t)b * NH + n * DH + j;
    hn[0] = hst;
    hn[(size_t)BB * NH] = cst;
}

extern "C" void kernel_launch(void* const* d_in, const int* in_sizes, int n_in,
                              void* d_out, int out_size) {
    const float* x   = (const float*)d_in[0];
    const float* Wih = (const float*)d_in[1];
    const float* Whh = (const float*)d_in[2];
    const float* bih = (const float*)d_in[3];
    const float* bhh = (const float*)d_in[4];
    float* out = (float*)d_out;

    cudaFuncSetAttribute(wlstm_xproj,
                         cudaFuncAttributeMaxDynamicSharedMemorySize, P1_SMEM);

    dim3 g1(TT / P1_TB, BB / 4, NL);   // (4, 8, 16) = 512 CTAs
    wlstm_xproj<<<g1, 512, P1_SMEM>>>(x, Wih, bih, bhh);
    wlstm_rec<<<NL * 8, 512>>>(Whh, out);
}

// round 8
// speedup vs baseline: 1.3422x; 1.0659x over previous
#include <cuda_runtime.h>
#include <cuda_fp16.h>
#include <cstdint>

// Problem dims
#define NL 16
#define DH 128
#define G4 512      // 4*H
#define BB 32
#define TT 512
#define NH 2048     // N*H
#define STRD 136    // padded halves per row (conflict-free LDS)

// x_proj scratch, GATE-INTERLEAVED: [n][t][b][j][gate] fp16, bias pre-added
__device__ __half g_xp16[(size_t)NL * TT * BB * G4];

// ---------------- mma.sync m16n8k16 (fp16 in, fp32 acc) ----------------
__device__ __forceinline__ void mma16816(float* d, const uint32_t* a,
                                         uint32_t b0, uint32_t b1) {
    asm volatile("mma.sync.aligned.m16n8k16.row.col.f32.f16.f16.f32 "
                 "{%0,%1,%2,%3}, {%4,%5,%6,%7}, {%8,%9}, {%0,%1,%2,%3};"
                 : "+f"(d[0]), "+f"(d[1]), "+f"(d[2]), "+f"(d[3])
                 : "r"(a[0]), "r"(a[1]), "r"(a[2]), "r"(a[3]), "r"(b0), "r"(b1));
}

// HW tanh (1 MUFU); sigma(x) = 0.5*tanh(x/2)+0.5
__device__ __forceinline__ float tanh_apx(float x) {
    float t;
    asm("tanh.approx.f32 %0, %1;" : "=f"(t) : "f"(x));
    return t;
}
__device__ __forceinline__ float sigm_apx(float x) {
    return fmaf(0.5f, tanh_apx(0.5f * x), 0.5f);
}

// =================================================================
// Phase 1: x_proj16[n][t][b][j][g] = W_ih[n].x + b_ih + b_hh
// grid (8 hb, 16 n) = 128 CTAs (1 wave), 512 threads.
// Per CTA: load W once; 16 tile-iters (4 batches x 4 t-tiles),
// double-buffered x; SMEM-staged coalesced stores.
// =================================================================
#define P1_TB 128
#define STGW 264   // stage row stride in words (256 + 8 pad)
#define P1_S_WS  0
#define P1_S_X0  (G4 * STRD * 2)                       // 139264
#define P1_S_X1  (P1_S_X0 + P1_TB * STRD * 2)          // +34816
#define P1_S_STG (P1_S_X1 + P1_TB * STRD * 2)          // +34816
#define P1_SMEM  (P1_S_STG + 8 * STGW * 4)             // +8448 = 217344

__global__ void __launch_bounds__(512, 1) wlstm_xproj(
    const float* __restrict__ x, const float* __restrict__ Wih,
    const float* __restrict__ bih, const float* __restrict__ bhh)
{
    extern __shared__ char p1smem[];
    __half*    ws  = (__half*)(p1smem + P1_S_WS);      // [512][STRD]
    __half*    xb0 = (__half*)(p1smem + P1_S_X0);      // [128][STRD]
    __half*    xb1 = (__half*)(p1smem + P1_S_X1);
    uint32_t*  stw = (uint32_t*)(p1smem + P1_S_STG);   // [8][STGW] words
    __half*    sth = (__half*)stw;

    const int tid = threadIdx.x, wid = tid >> 5, lane = tid & 31;
    const int g0 = lane >> 2, cq = lane & 3;
    const int n = blockIdx.y, hb = blockIdx.x;

    // ---- W_ih[n] fp32 -> fp16 SMEM
    const float4* W4 = (const float4*)(Wih + (size_t)n * G4 * DH);
#pragma unroll 4
    for (int i = tid; i < G4 * DH / 4; i += 512) {
        float4 w = W4[i];
        int r = i >> 5, k = (i & 31) * 4;
        __half2 h01 = __floats2half2_rn(w.x, w.y);
        __half2 h23 = __floats2half2_rn(w.z, w.w);
        uint2 v = { *(uint32_t*)&h01, *(uint32_t*)&h23 };
        *(uint2*)(ws + r * STRD + k) = v;
    }

    // x tile loader: unit u -> (bl = u>>2, tt = u&3)
    auto load_tile = [&](int u, __half* dst) {
        int b = hb * 4 + (u >> 2), t0 = (u & 3) * P1_TB;
#pragma unroll 4
        for (int i = tid; i < P1_TB * DH / 4; i += 512) {
            int tl = i >> 5, c4 = (i & 31) * 4;
            float4 w = *(const float4*)(x + ((size_t)b * TT + t0 + tl) * NH + n * DH + c4);
            __half2 h01 = __floats2half2_rn(w.x, w.y);
            __half2 h23 = __floats2half2_rn(w.z, w.w);
            uint2 v = { *(uint32_t*)&h01, *(uint32_t*)&h23 };
            *(uint2*)(dst + tl * STRD + c4) = v;
        }
    };
    load_tile(0, xb0);
    __syncthreads();

    // ---- A-fragments: warp wid owns m-tiles {2*wid, 2*wid+1}
    uint32_t a[2][8][4];
    const uint32_t* ws32 = (const uint32_t*)ws;
#pragma unroll
    for (int ti = 0; ti < 2; ti++) {
        int r0 = (2 * wid + ti) * 16 + g0;
#pragma unroll
        for (int kc = 0; kc < 8; kc++) {
            int kw = kc * 8 + cq;
            a[ti][kc][0] = ws32[r0 * (STRD / 2) + kw];
            a[ti][kc][1] = ws32[(r0 + 8) * (STRD / 2) + kw];
            a[ti][kc][2] = ws32[r0 * (STRD / 2) + kw + 4];
            a[ti][kc][3] = ws32[(r0 + 8) * (STRD / 2) + kw + 4];
        }
    }
    float bsv[2][2];
#pragma unroll
    for (int ti = 0; ti < 2; ti++) {
        int r0 = (2 * wid + ti) * 16 + g0;
        bsv[ti][0] = bih[n * G4 + r0]     + bhh[n * G4 + r0];
        bsv[ti][1] = bih[n * G4 + r0 + 8] + bhh[n * G4 + r0 + 8];
    }

    for (int u = 0; u < 16; u++) {
        const __half* xs = (u & 1) ? xb1 : xb0;
        if (u < 15) load_tile(u + 1, (u & 1) ? xb0 : xb1);

        int b = hb * 4 + (u >> 2), t0 = (u & 3) * P1_TB;
        __half* ob = g_xp16 + ((size_t)(n * TT + t0) * BB + b) * G4;
        const uint32_t* xs32 = (const uint32_t*)xs;

        for (int nt = 0; nt < 16; nt++) {
            float d[2][4];
#pragma unroll
            for (int ti = 0; ti < 2; ti++)
#pragma unroll
                for (int q = 0; q < 4; q++) d[ti][q] = 0.0f;

            int col = nt * 8 + g0;
#pragma unroll
            for (int kc = 0; kc < 8; kc++) {
                uint32_t b0 = xs32[col * (STRD / 2) + kc * 8 + cq];
                uint32_t b1 = xs32[col * (STRD / 2) + kc * 8 + cq + 4];
#pragma unroll
                for (int ti = 0; ti < 2; ti++) mma16816(d[ti], a[ti][kc], b0, b1);
            }
            // stage slice [8 t][j*4+gate] with bias folded
            int tb0 = 2 * cq;
#pragma unroll
            for (int ti = 0; ti < 2; ti++) {
                int r0 = (2 * wid + ti) * 16 + g0;
                int j = r0 & 127, gate = r0 >> 7;
                sth[(size_t)tb0 * (2 * STGW) + j * 4 + gate]             = __float2half(d[ti][0] + bsv[ti][0]);
                sth[(size_t)(tb0 + 1) * (2 * STGW) + j * 4 + gate]       = __float2half(d[ti][1] + bsv[ti][0]);
                sth[(size_t)tb0 * (2 * STGW) + (j + 8) * 4 + gate]       = __float2half(d[ti][2] + bsv[ti][1]);
                sth[(size_t)(tb0 + 1) * (2 * STGW) + (j + 8) * 4 + gate] = __float2half(d[ti][3] + bsv[ti][1]);
            }
            __syncthreads();
            // cooperative coalesced store: thread (tl = tid>>6, w4 = tid&63)
            {
                int tl = tid >> 6, w4 = tid & 63;
                uint4 v = *(const uint4*)(stw + tl * STGW + w4 * 4);
                *(uint4*)(ob + (size_t)(nt * 8 + tl) * (BB * G4) + w4 * 8) = v;
            }
            __syncthreads();
        }
    }
}

// =================================================================
// Phase 2: persistent recurrence (R7 structure). grid 128, 512 thr.
// W_hh in regs; z via SMEM; one state per thread; all-approx;
// x_proj loaded as one uint2 (4 gates) per thread per step.
// =================================================================
#define ZSTR 520

__global__ void __launch_bounds__(512, 1) wlstm_rec(
    const float* __restrict__ Whh, float* __restrict__ out)
{
    __shared__ __half hs[2][8][STRD];   // double-buffered h tile [buf][bcol][j]
    __shared__ float  zs[4 * ZSTR];     // z exchange: [batch][512 gate rows]

    const int tid = threadIdx.x, wid = tid >> 5, lane = tid & 31;
    const int g0 = lane >> 2, cq = lane & 3;
    const int n = blockIdx.x >> 3, bc = blockIdx.x & 7;

    for (int i = tid; i < 2 * 8 * STRD; i += 512) ((__half*)hs)[i] = __float2half(0.0f);

    // ---- W_hh[n] -> A-fragments (warp wid owns m-tiles {wid, wid+16})
    uint32_t a[2][8][4];
    const float* W = Whh + (size_t)n * G4 * DH;
#pragma unroll
    for (int ti = 0; ti < 2; ti++) {
        int r0 = (wid + 16 * ti) * 16 + g0;
#pragma unroll
        for (int kc = 0; kc < 8; kc++) {
            int k0 = kc * 16 + cq * 2;
            float2 w00 = *(const float2*)(W + (size_t)r0 * DH + k0);
            float2 w10 = *(const float2*)(W + (size_t)(r0 + 8) * DH + k0);
            float2 w01 = *(const float2*)(W + (size_t)r0 * DH + k0 + 8);
            float2 w11 = *(const float2*)(W + (size_t)(r0 + 8) * DH + k0 + 8);
            __half2 h00 = __floats2half2_rn(w00.x, w00.y);
            __half2 h10 = __floats2half2_rn(w10.x, w10.y);
            __half2 h01 = __floats2half2_rn(w01.x, w01.y);
            __half2 h11 = __floats2half2_rn(w11.x, w11.y);
            a[ti][kc][0] = *(uint32_t*)&h00;
            a[ti][kc][1] = *(uint32_t*)&h10;
            a[ti][kc][2] = *(uint32_t*)&h01;
            a[ti][kc][3] = *(uint32_t*)&h11;
        }
    }

    const int j  = tid & 127;
    const int bl = tid >> 7;
    const int b  = bc * 4 + bl;

    // interleaved: gates of (t, b, j) contiguous -> one 8B load
    const __half* xq = g_xp16 + ((size_t)(n * TT) * BB + b) * G4 + j * 4;
    float* ob = out + (size_t)b * TT * NH + n * DH + j;

    float xpa[4], xpb[4];
    {
        uint2 v = *(const uint2*)xq;
        float2 f01 = __half22float2(*(__half2*)&v.x);
        float2 f23 = __half22float2(*(__half2*)&v.y);
        xpa[0] = f01.x; xpa[1] = f01.y; xpa[2] = f23.x; xpa[3] = f23.y;
    }

    float cst = 0.0f, hst = 0.0f;
    __syncthreads();

    auto step = [&](int t, float (&xpc)[4], float (&xpn)[4]) {
        // prefetch x_proj(t+1) early (hidden behind mma)
        if (t + 1 < TT) {
            uint2 v = *(const uint2*)(xq + (size_t)(t + 1) * (BB * G4));
            float2 f01 = __half22float2(*(__half2*)&v.x);
            float2 f23 = __half22float2(*(__half2*)&v.y);
            xpn[0] = f01.x; xpn[1] = f01.y; xpn[2] = f23.x; xpn[3] = f23.y;
        }
        // ---- z = W_hh . h_{t-1}
        const uint32_t* hb = (const uint32_t*)hs[t & 1];
        float d[2][4];
#pragma unroll
        for (int ti = 0; ti < 2; ti++)
#pragma unroll
            for (int q = 0; q < 4; q++) d[ti][q] = 0.0f;
#pragma unroll
        for (int kc = 0; kc < 8; kc++) {
            uint32_t b0 = hb[g0 * (STRD / 2) + kc * 8 + cq];
            uint32_t b1 = hb[g0 * (STRD / 2) + kc * 8 + cq + 4];
#pragma unroll
            for (int ti = 0; ti < 2; ti++) mma16816(d[ti], a[ti][kc], b0, b1);
        }
        // stash z for real batches (D cols 0..3 <-> cq 0,1)
        if (cq < 2) {
#pragma unroll
            for (int ti = 0; ti < 2; ti++) {
                int r0 = (wid + 16 * ti) * 16 + g0;
                zs[(2 * cq) * ZSTR + r0]         = d[ti][0];
                zs[(2 * cq + 1) * ZSTR + r0]     = d[ti][1];
                zs[(2 * cq) * ZSTR + r0 + 8]     = d[ti][2];
                zs[(2 * cq + 1) * ZSTR + r0 + 8] = d[ti][3];
            }
        }
        __syncthreads();   // z visible to all

        // ---- epilogue: one state per thread (all-approx activations)
        float zi = zs[bl * ZSTR + j]       + xpc[0];
        float zf = zs[bl * ZSTR + 128 + j] + xpc[1];
        float zg = zs[bl * ZSTR + 256 + j] + xpc[2];
        float zo = zs[bl * ZSTR + 384 + j] + xpc[3];
        float ig = sigm_apx(zi);
        float fg = sigm_apx(zf);
        float gg = tanh_apx(zg);
        float og = sigm_apx(zo);
        cst = fg * cst + ig * gg;
        hst = og * tanh_apx(cst);

        ob[(size_t)t * NH] = hst;
        hs[(t + 1) & 1][bl][j] = __float2half(hst);
        __syncthreads();   // hs(t) visible + zs reads done before next mma
    };

    for (int t = 0; t < TT; t += 2) {
        step(t, xpa, xpb);
        step(t + 1, xpb, xpa);
    }

    // h_n, c_n: out = [output | h_n | c_n]
    float* hn = out + (size_t)BB * TT * NH + (size_t)b * NH + n * DH + j;
    hn[0] = hst;
    hn[(size_t)BB * NH] = cst;
}

extern "C" void kernel_launch(void* const* d_in, const int* in_sizes, int n_in,
                              void* d_out, int out_size) {
    const float* x   = (const float*)d_in[0];
    const float* Wih = (const float*)d_in[1];
    const float* Whh = (const float*)d_in[2];
    const float* bih = (const float*)d_in[3];
    const float* bhh = (const float*)d_in[4];
    float* out = (float*)d_out;

    cudaFuncSetAttribute(wlstm_xproj,
                         cudaFuncAttributeMaxDynamicSharedMemorySize, P1_SMEM);

    dim3 g1(8, NL);   // 128 CTAs, 1 wave
    wlstm_xproj<<<g1, 512, P1_SMEM>>>(x, Wih, bih, bhh);
    wlstm_rec<<<NL * 8, 512>>>(Whh, out);
}